// round 15
// baseline (speedup 1.0000x reference)
#include <cuda_runtime.h>

#define FIN 128
#define HD  128
#define C3  384
#define H1D 256
#define OUTD 40
#define NMAX 50000
#define EMAX 800000

// fragment-interleaved weight pool offsets (in float4 units)
// per matrix: nbp * (K/8) * 32 float4s, nbp = padded Nc/8
#define OFF4_WCAT 0                        // K=128, Nc=384, nbp=48 -> 24576
#define OFF4_WSL  24576                    // K=128, Nc=128, nbp=16 ->  8192
#define OFF4_W1   32768                    // K=384, Nc=256, nbp=32 -> 49152
#define OFF4_W2   81920                    // K=256, Nc=128, nbp=16 -> 16384
#define OFF4_W3   98304                    // K=128, Nc=40->64, nbp=8 -> 4096
#define BTOT4     102400

// ---------------- scratch (static device globals; no allocation allowed) ----
__device__ __align__(16) float g_H[(size_t)NMAX * C3];     // [x@Wgat | x@Wgcn | x@Wsage_r]
__device__ __align__(16) float g_hcat[(size_t)NMAX * C3];  // [gat_out | gcn_out | sage_out]
__device__ __align__(16) float g_sage[(size_t)NMAX * HD];  // mean of x over in-neighbors
__device__ __align__(16) float g_h1[(size_t)NMAX * H1D];
__device__ __align__(16) float g_h2[(size_t)NMAX * HD];
__device__ __align__(16) float4 g_Bfrag[BTOT4];            // mma-fragment-ordered weights
__device__ __align__(16) float4 g_csr[EMAX];               // {src, wg, wc, -}
__device__ float g_as[NMAX], g_ad[NMAX], g_dinv[NMAX], g_es[NMAX];
__device__ int   g_deg[NMAX];
__device__ int   g_off[NMAX + 1], g_cur[NMAX];
__device__ float g_sums[C3], g_sumsq[C3], g_scale[C3], g_shift[C3];
__device__ int   g_is64;   // 1 if edge_index buffer is int64, 0 if int32

// device-side scratch-buffer resolver (host never needs the addresses)
#define TAG_NONE  (-1)
#define TAG_H     0
#define TAG_HCAT  1
#define TAG_SAGE  2
#define TAG_H1    3
#define TAG_H2    4
__device__ __forceinline__ float* buf(int tag) {
    switch (tag) {
        case TAG_H:    return g_H;
        case TAG_HCAT: return g_hcat;
        case TAG_SAGE: return g_sage;
        case TAG_H1:   return g_h1;
        case TAG_H2:   return g_h2;
    }
    return nullptr;
}

__device__ __forceinline__ float leaky(float x) { return x > 0.f ? x : 0.2f * x; }

// edge-index accessor robust to int32-vs-int64 storage
__device__ __forceinline__ int ld_idx(const void* ei, size_t i) {
    if (g_is64) return (int)((const long long*)ei)[i];
    return ((const int*)ei)[i];
}

// ---------------- tf32 / mma / cp.async helpers -----------------------------
__device__ __forceinline__ unsigned f32_tf32(float f) {
    unsigned r; asm("cvt.rna.tf32.f32 %0, %1;" : "=r"(r) : "f"(f)); return r;
}
// precise split (pre-pack only)
__device__ __forceinline__ void split_tf32(float v, unsigned& hi, unsigned& lo) {
    hi = f32_tf32(v);
    lo = f32_tf32(v - __uint_as_float(hi));
}
// fast split: truncate to tf32 bits (LOP3) + exact remainder (FADD).
__device__ __forceinline__ void split_fast(float v, unsigned& hi, unsigned& lo) {
    hi = __float_as_uint(v) & 0xffffe000u;
    lo = __float_as_uint(v - __uint_as_float(hi));
}
__device__ __forceinline__ void mma8(float* c, const unsigned* a, const unsigned* b) {
    asm volatile(
        "mma.sync.aligned.m16n8k8.row.col.f32.tf32.tf32.f32 "
        "{%0,%1,%2,%3}, {%4,%5,%6,%7}, {%8,%9}, {%0,%1,%2,%3};"
        : "+f"(c[0]), "+f"(c[1]), "+f"(c[2]), "+f"(c[3])
        : "r"(a[0]), "r"(a[1]), "r"(a[2]), "r"(a[3]), "r"(b[0]), "r"(b[1]));
}
__device__ __forceinline__ void cp16(unsigned dst, const void* src, int bytes) {
    asm volatile("cp.async.cg.shared.global [%0], [%1], 16, %2;"
                 :: "r"(dst), "l"(src), "r"(bytes));
}
__device__ __forceinline__ void cp_commit() { asm volatile("cp.async.commit_group;"); }
__device__ __forceinline__ void cp_wait0()  { asm volatile("cp.async.wait_group 0;" ::: "memory"); }

// ---------------- dtype detect: odd 32-bit words all zero  <=>  int64 -------
__global__ void detect_idx(const void* ei, int E)
{
    const int* w = (const int*)ei;
    int n = E < 128 ? E : 128;
    int t = threadIdx.x;            // 128 threads
    int nz = 0;
    if (t < n) nz = (w[2 * t + 1] != 0) ? 1 : 0;
    #pragma unroll
    for (int o = 16; o; o >>= 1) nz += __shfl_xor_sync(0xffffffffu, nz, o);
    __shared__ int sh[4];
    if ((t & 31) == 0) sh[t >> 5] = nz;
    __syncthreads();
    if (t == 0) g_is64 = ((sh[0] + sh[1] + sh[2] + sh[3]) == 0) ? 1 : 0;
}

// ---------------- zero the fragment pool (for padded regions) ---------------
__global__ void zero_pool()
{
    int i = blockIdx.x * blockDim.x + threadIdx.x;
    if (i < BTOT4) g_Bfrag[i] = make_float4(0.f, 0.f, 0.f, 0.f);
}

// write one weight element into the fragment-interleaved pool
__device__ __forceinline__ void frag_store(int off4, int kctot, int k, int n, float v)
{
    unsigned hi, lo; split_tf32(v, hi, lo);
    int kc8 = k >> 3, r = k & 7, tig = r & 3, slot = r >> 2;
    int nb = n >> 3, gid = n & 7;
    int lane = gid * 4 + tig;
    float* p = (float*)(g_Bfrag + off4 + ((size_t)nb * kctot + kc8) * 32 + lane);
    p[slot]     = __uint_as_float(hi);
    p[2 + slot] = __uint_as_float(lo);
}

// ---------------- pack WCAT = [W_gat | W_gcn | W_sage_r] --------------------
__global__ void pack_split_w(const float* __restrict__ a, const float* __restrict__ b,
                             const float* __restrict__ c)
{
    int i = blockIdx.x * blockDim.x + threadIdx.x;
    if (i >= FIN * C3) return;
    int k = i / C3, j = i % C3;
    float v;
    if (j < 128)      v = a[k * HD + j];
    else if (j < 256) v = b[k * HD + j - 128];
    else              v = c[k * HD + j - 256];
    frag_store(OFF4_WCAT, FIN / 8, k, j, v);
}

// ---------------- split an external weight matrix [K, Nc] row-major ---------
__global__ void split_mat(const float* __restrict__ src, int off4, int K, int Nc)
{
    int i = blockIdx.x * blockDim.x + threadIdx.x;
    if (i >= K * Nc) return;
    int k = i / Nc, n = i % Nc;
    frag_store(off4, K >> 3, k, n, src[i]);
}

// ---------------- node init: a_src/a_dst dots, seeds ------------------------
__global__ void node_init(const float* __restrict__ att_s,
                          const float* __restrict__ att_d, int N)
{
    int gw   = (blockIdx.x * blockDim.x + threadIdx.x) >> 5;
    int lane = threadIdx.x & 31;
    if (gw >= N) return;
    float4 h = ((const float4*)(g_H + (size_t)gw * C3))[lane];   // first 128 = gat h
    float4 s = ((const float4*)att_s)[lane];
    float4 d = ((const float4*)att_d)[lane];
    float ps = h.x * s.x + h.y * s.y + h.z * s.z + h.w * s.w;
    float pd = h.x * d.x + h.y * d.y + h.z * d.z + h.w * d.w;
    #pragma unroll
    for (int o = 16; o; o >>= 1) {
        ps += __shfl_xor_sync(0xffffffffu, ps, o);
        pd += __shfl_xor_sync(0xffffffffu, pd, o);
    }
    if (lane == 0) {
        g_as[gw] = ps; g_ad[gw] = pd;
        g_deg[gw] = 1;                      // self loop counts for GCN degree
    }
}

// ---------------- edge pass 1: degree only ----------------------------------
// GAT softmax without max-subtraction: logits bounded (|e| << 80) so exp()
// cannot overflow; alpha = exp(e)/sum exp(e) is mathematically identical.
__global__ void edge_pass1(const void* __restrict__ ei, int E)
{
    int e = blockIdx.x * blockDim.x + threadIdx.x;
    if (e >= E) return;
    int d = ld_idx(ei, (size_t)E + e);
    atomicAdd(&g_deg[d], 1);     // in-degree+1; CSR count = deg-1
}

// ---------------- node scalars: es (self-loop weight), dinv ------------------
__global__ void node_seed(int N)
{
    int i = blockIdx.x * blockDim.x + threadIdx.x;
    if (i >= N) return;
    g_es[i]   = expf(leaky(g_as[i] + g_ad[i]));
    g_dinv[i] = rsqrtf((float)g_deg[i]);
}

// ---------------- exclusive scan of (deg-1) -> off, cur (single block) ------
__global__ void scan_cnt(int N, int E)
{
    __shared__ int part[1024];
    int t = threadIdx.x;
    int chunk = (N + 1023) / 1024;
    int lo = t * chunk;
    int hi = lo + chunk; if (hi > N) hi = N;
    int s = 0;
    for (int i = lo; i < hi; i++) s += g_deg[i] - 1;
    part[t] = s;
    __syncthreads();
    for (int o = 1; o < 1024; o <<= 1) {
        int v = (t >= o) ? part[t - o] : 0;
        __syncthreads();
        part[t] += v;
        __syncthreads();
    }
    int base = (t == 0) ? 0 : part[t - 1];
    for (int i = lo; i < hi; i++) {
        g_off[i] = base;
        g_cur[i] = base;
        base += g_deg[i] - 1;
    }
    if (t == 0) g_off[N] = E;
}

// ---------------- fill CSR: per-edge meta {src, wg, wc} ---------------------
__global__ void edge_fill(const void* __restrict__ ei, int E)
{
    int e = blockIdx.x * blockDim.x + threadIdx.x;
    if (e >= E) return;
    int s = ld_idx(ei, e);
    int d = ld_idx(ei, (size_t)E + e);
    float wg = expf(leaky(g_as[s] + g_ad[d]));
    float wc = g_dinv[s] * g_dinv[d];
    int pos = atomicAdd(&g_cur[d], 1);
    g_csr[pos] = make_float4(__int_as_float(s), wg, wc, 0.f);
}

// ---------------- gather: one warp per dst node (no float atomics) ----------
__global__ void gather(const float* __restrict__ x,
                       const float* __restrict__ bg,
                       const float* __restrict__ bc, int N)
{
    int gw   = (blockIdx.x * blockDim.x + threadIdx.x) >> 5;
    int lane = threadIdx.x & 31;
    if (gw >= N) return;

    const float4* hr = (const float4*)(g_H + (size_t)gw * C3);
    float es   = g_es[gw];
    float dinv = g_dinv[gw];
    float d2   = dinv * dinv;

    // self-loop seeds
    float4 hg = hr[lane];
    float4 hc = hr[lane + 32];
    float ag0 = es * hg.x, ag1 = es * hg.y, ag2 = es * hg.z, ag3 = es * hg.w;
    float ac0 = d2 * hc.x, ac1 = d2 * hc.y, ac2 = d2 * hc.z, ac3 = d2 * hc.w;
    float ax0 = 0.f, ax1 = 0.f, ax2 = 0.f, ax3 = 0.f;
    float denom = es;

    int lo = g_off[gw], hi = g_off[gw + 1];
    for (int j = lo; j < hi; j++) {
        float4 meta;
        if (lane == 0) meta = g_csr[j];
        int   s  = __shfl_sync(0xffffffffu, __float_as_int(meta.x), 0);
        float wg = __shfl_sync(0xffffffffu, meta.y, 0);
        float wc = __shfl_sync(0xffffffffu, meta.z, 0);
        const float4* hs = (const float4*)(g_H + (size_t)s * C3);
        float4 vg = hs[lane];
        float4 vc = hs[lane + 32];
        float4 vx = ((const float4*)(x + (size_t)s * FIN))[lane];
        ag0 = fmaf(wg, vg.x, ag0); ag1 = fmaf(wg, vg.y, ag1);
        ag2 = fmaf(wg, vg.z, ag2); ag3 = fmaf(wg, vg.w, ag3);
        ac0 = fmaf(wc, vc.x, ac0); ac1 = fmaf(wc, vc.y, ac1);
        ac2 = fmaf(wc, vc.z, ac2); ac3 = fmaf(wc, vc.w, ac3);
        ax0 += vx.x; ax1 += vx.y; ax2 += vx.z; ax3 += vx.w;
        denom += wg;
    }

    float inv = 1.f / denom;
    float ci  = 1.f / fmaxf((float)(hi - lo), 1.f);
    float4 b  = ((const float4*)bg)[lane];
    float4 b2 = ((const float4*)bc)[lane];
    float4* oc = (float4*)(g_hcat + (size_t)gw * C3);
    oc[lane]      = make_float4(ag0 * inv + b.x,  ag1 * inv + b.y,
                                ag2 * inv + b.z,  ag3 * inv + b.w);
    oc[lane + 32] = make_float4(ac0 + b2.x, ac1 + b2.y, ac2 + b2.z, ac3 + b2.w);
    ((float4*)(g_sage + (size_t)gw * HD))[lane] =
        make_float4(ax0 * ci, ax1 * ci, ax2 * ci, ax3 * ci);
}

// ---------------- BatchNorm stats ------------------------------------------
__global__ void bn_zero()
{
    int t = threadIdx.x;
    if (t < C3) { g_sums[t] = 0.f; g_sumsq[t] = 0.f; }
}

__global__ void bn_stats(int N)
{
    int c = blockIdx.x * 32 + threadIdx.x;
    float s = 0.f, q = 0.f;
    for (int r = blockIdx.y * blockDim.y + threadIdx.y; r < N; r += gridDim.y * blockDim.y) {
        float v = g_hcat[(size_t)r * C3 + c];
        s += v; q += v * v;
    }
    __shared__ float sh[8][33], shq[8][33];
    sh[threadIdx.y][threadIdx.x] = s;
    shq[threadIdx.y][threadIdx.x] = q;
    __syncthreads();
    if (threadIdx.y == 0) {
        #pragma unroll
        for (int j = 1; j < 8; j++) { s += sh[j][threadIdx.x]; q += shq[j][threadIdx.x]; }
        atomicAdd(&g_sums[c], s);
        atomicAdd(&g_sumsq[c], q);
    }
}

__global__ void bn_scale(const float* __restrict__ gamma,
                         const float* __restrict__ beta, int N)
{
    int c = threadIdx.x;
    if (c >= C3) return;
    float invN = 1.f / (float)N;
    float mu  = g_sums[c] * invN;
    float var = g_sumsq[c] * invN - mu * mu;
    float sc  = gamma[c] * rsqrtf(var + 1e-5f);
    g_scale[c] = sc;
    g_shift[c] = beta[c] - mu * sc;
}

// ---------------- 3xTF32 tensor-core GEMM (fragment-pool B) -----------------
// C[M,Nc] = act(A[M,K]) @ B[K,Nc] (+bias) (+Dadd)
// B lives in g_Bfrag (mma-fragment-interleaved hi/lo), loaded with one
// LDG.128 per (kk, nt) from L2; no B smem at all.
// 128x64 block tile, 8 warps (4x2), warp tile 32x32 via m16n8k8 tf32 mma.
// MODE 0: identity ; MODE 1: relu(A) ; MODE 2: relu(A*g_scale[k]+g_shift[k])
// Requires K % 16 == 0.
#define ASTR 20   // A smem row stride (floats): conflict-free, 16B-aligned
template<int MODE>
__global__ void __launch_bounds__(256) gemm_tc(
    const float* __restrict__ Aext, int Atag, int Aoff, int lda,
    int Boff4,
    float* __restrict__ Cext, int Ctag, int Coff, int ldc,
    int M, int Nc, int K,
    const float* __restrict__ bias,
    int Dtag, int Doff, int ldd)
{
    const float* A  = Aext ? Aext : (const float*)(buf(Atag) + Aoff);
    float*       C  = Cext ? Cext : (buf(Ctag) + Coff);
    const float* Dadd = (Dtag >= 0) ? (const float*)(buf(Dtag) + Doff) : nullptr;

    __shared__ float As[2][128 * ASTR];

    const int t    = threadIdx.x;
    const int lane = t & 31, w = t >> 5;
    const int wm = w >> 1, wn = w & 1;          // 4x2 warp grid
    const int gid = lane >> 2, tig = lane & 3;  // fragment coords
    const int rowBase = blockIdx.x * 128;
    const int colBase = blockIdx.y * 64;
    const int kctot = K >> 3;

    // per-nt fragment pointers (advance by 32 float4 per k-chunk-of-8)
    const float4* __restrict__ Bf = g_Bfrag + Boff4 + lane;
    const float4* bp[4];
    #pragma unroll
    for (int nt = 0; nt < 4; nt++) {
        int nbg = (colBase >> 3) + wn * 4 + nt;
        bp[nt] = Bf + (size_t)nbg * kctot * 32;
    }

    float acc[2][4][4];
    #pragma unroll
    for (int i = 0; i < 2; i++)
        #pragma unroll
        for (int j = 0; j < 4; j++)
            #pragma unroll
            for (int q = 0; q < 4; q++) acc[i][j][q] = 0.f;

    // cp.async coordinates for A (fixed per thread)
    const int ar0 = t >> 2;                 // A rows 0..63
    const int ar1 = (t + 256) >> 2;         // A rows 64..127
    const int akc = (t & 3) << 2;           // A k offset {0,4,8,12}
    const int gAr0 = rowBase + ar0, gAr1 = rowBase + ar1;
    const int szA0 = (gAr0 < M) ? 16 : 0;
    const int szA1 = (gAr1 < M) ? 16 : 0;
    const unsigned dA0 = (unsigned)__cvta_generic_to_shared(&As[0][ar0 * ASTR + akc]);
    const unsigned dA1 = (unsigned)__cvta_generic_to_shared(&As[0][ar1 * ASTR + akc]);
    const unsigned stA = (unsigned)(128 * ASTR * 4);   // stage byte stride

    const int nch = K >> 4;

    // prefetch A chunk 0 into stage 0
    cp16(dA0, A + (size_t)gAr0 * lda + akc, szA0);
    cp16(dA1, A + (size_t)gAr1 * lda + akc, szA1);
    cp_commit();
    cp_wait0();
    __syncthreads();

    int st = 0;
    for (int c = 0; c < nch; c++) {
        int kb = c << 4;
        if (c + 1 < nch) {
            int kn = kb + 16;
            unsigned so = (st ^ 1) ? stA : 0u;
            cp16(dA0 + so, A + (size_t)gAr0 * lda + kn + akc, szA0);
            cp16(dA1 + so, A + (size_t)gAr1 * lda + kn + akc, szA1);
            cp_commit();
        }
        const float* Ab = As[st];
        #pragma unroll
        for (int kk = 0; kk < 16; kk += 8) {
            const int kc = (kb + kk) >> 3;
            // B fragments: one LDG.128 per nt (hi pair + lo pair)
            unsigned bh[4][2], bl[4][2];
            #pragma unroll
            for (int nt = 0; nt < 4; nt++) {
                float4 q = __ldg(bp[nt] + (size_t)kc * 32);
                bh[nt][0] = __float_as_uint(q.x);
                bh[nt][1] = __float_as_uint(q.y);
                bl[nt][0] = __float_as_uint(q.z);
                bl[nt][1] = __float_as_uint(q.w);
            }
            unsigned ah[2][4], al[2][4];
            #pragma unroll
            for (int mt = 0; mt < 2; mt++) {
                const float* p = Ab + (wm * 32 + mt * 16 + gid) * ASTR + kk + tig;
                float v0 = p[0], v1 = p[8 * ASTR], v2 = p[4], v3 = p[8 * ASTR + 4];
                if (MODE == 1) {
                    v0 = fmaxf(v0, 0.f); v1 = fmaxf(v1, 0.f);
                    v2 = fmaxf(v2, 0.f); v3 = fmaxf(v3, 0.f);
                }
                if (MODE == 2) {
                    int k0g = kb + kk + tig, k1g = k0g + 4;
                    float s0 = g_scale[k0g], h0 = g_shift[k0g];
                    float s1 = g_scale[k1g], h1 = g_shift[k1g];
                    v0 = fmaxf(fmaf(v0, s0, h0), 0.f);
                    v1 = fmaxf(fmaf(v1, s0, h0), 0.f);
                    v2 = fmaxf(fmaf(v2, s1, h1), 0.f);
                    v3 = fmaxf(fmaf(v3, s1, h1), 0.f);
                }
                split_fast(v0, ah[mt][0], al[mt][0]);
                split_fast(v1, ah[mt][1], al[mt][1]);
                split_fast(v2, ah[mt][2], al[mt][2]);
                split_fast(v3, ah[mt][3], al[mt][3]);
            }
            #pragma unroll
            for (int mt = 0; mt < 2; mt++)
                #pragma unroll
                for (int nt = 0; nt < 4; nt++) {
                    mma8(acc[mt][nt], ah[mt], bh[nt]);
                    mma8(acc[mt][nt], ah[mt], bl[nt]);
                    mma8(acc[mt][nt], al[mt], bh[nt]);
                }
        }
        if (c + 1 < nch) {
            cp_wait0();
            __syncthreads();
            st ^= 1;
        }
    }

    // epilogue
    #pragma unroll
    for (int mt = 0; mt < 2; mt++) {
        int r0 = rowBase + wm * 32 + mt * 16 + gid;
        int r1 = r0 + 8;
        #pragma unroll
        for (int nt = 0; nt < 4; nt++) {
            int c0 = colBase + wn * 32 + nt * 8 + 2 * tig;
            if (c0 >= Nc) continue;
            float b0v = bias ? bias[c0] : 0.f;
            float b1v = bias ? bias[c0 + 1] : 0.f;
            if (r0 < M) {
                float v0 = acc[mt][nt][0] + b0v;
                float v1 = acc[mt][nt][1] + b1v;
                if (Dadd) {
                    v0 += Dadd[(size_t)r0 * ldd + c0];
                    v1 += Dadd[(size_t)r0 * ldd + c0 + 1];
                }
                C[(size_t)r0 * ldc + c0]     = v0;
                C[(size_t)r0 * ldc + c0 + 1] = v1;
            }
            if (r1 < M) {
                float v2 = acc[mt][nt][2] + b0v;
                float v3 = acc[mt][nt][3] + b1v;
                if (Dadd) {
                    v2 += Dadd[(size_t)r1 * ldd + c0];
                    v3 += Dadd[(size_t)r1 * ldd + c0 + 1];
                }
                C[(size_t)r1 * ldc + c0]     = v2;
                C[(size_t)r1 * ldc + c0 + 1] = v3;
            }
        }
    }
}

// ---------------- launch ----------------------------------------------------
extern "C" void kernel_launch(void* const* d_in, const int* in_sizes, int n_in,
                              void* d_out, int out_size)
{
    const float* x        = (const float*)d_in[0];
    const void*  ei       = d_in[1];
    const float* W_gat    = (const float*)d_in[2];
    const float* att_src  = (const float*)d_in[3];
    const float* att_dst  = (const float*)d_in[4];
    const float* b_gat    = (const float*)d_in[5];
    const float* W_gcn    = (const float*)d_in[6];
    const float* b_gcn    = (const float*)d_in[7];
    const float* W_sage_l = (const float*)d_in[8];
    const float* b_sage_l = (const float*)d_in[9];
    const float* W_sage_r = (const float*)d_in[10];
    const float* W1       = (const float*)d_in[11];
    const float* b1       = (const float*)d_in[12];
    const float* W2       = (const float*)d_in[13];
    const float* b2       = (const float*)d_in[14];
    const float* W3       = (const float*)d_in[15];
    const float* b3       = (const float*)d_in[16];
    const float* gamma    = (const float*)d_in[17];
    const float* beta     = (const float*)d_in[18];
    float* out = (float*)d_out;

    int N = in_sizes[0] / FIN;
    int E = in_sizes[1] / 2;

    // 0) build fragment-interleaved weight pool (zero first for padding)
    zero_pool<<<(BTOT4 + 255) / 256, 256>>>();
    pack_split_w<<<(FIN * C3 + 255) / 256, 256>>>(W_gat, W_gcn, W_sage_r);
    split_mat<<<(HD * HD + 255) / 256, 256>>>(W_sage_l, OFF4_WSL, HD, HD);
    split_mat<<<(C3 * H1D + 255) / 256, 256>>>(W1, OFF4_W1, C3, H1D);
    split_mat<<<(H1D * HD + 255) / 256, 256>>>(W2, OFF4_W2, H1D, HD);
    split_mat<<<(HD * OUTD + 255) / 256, 256>>>(W3, OFF4_W3, HD, OUTD);

    int gm = (N + 127) / 128;

    // 1) H = x @ [W_gat | W_gcn | W_sage_r]  (one merged GEMM, Nc=384)
    gemm_tc<0><<<dim3(gm, 6), 256>>>(x, TAG_NONE, 0, FIN, OFF4_WCAT,
                                     nullptr, TAG_H, 0, C3, N, C3, FIN,
                                     nullptr, TAG_NONE, 0, 0);

    // 2-6) graph aggregation via CSR gather
    detect_idx<<<1, 128>>>(ei, E);
    node_init<<<(N + 7) / 8, 256>>>(att_src, att_dst, N);
    edge_pass1<<<(E + 255) / 256, 256>>>(ei, E);
    node_seed<<<(N + 255) / 256, 256>>>(N);
    scan_cnt<<<1, 1024>>>(N, E);
    edge_fill<<<(E + 255) / 256, 256>>>(ei, E);
    gather<<<(N + 7) / 8, 256>>>(x, b_gat, b_gcn, N);

    // 7) sage: hcat[:,256:384] = mean @ W_sage_l + b_sage_l + (x@W_sage_r)
    gemm_tc<0><<<dim3(gm, 2), 256>>>(nullptr, TAG_SAGE, 0, HD, OFF4_WSL,
                                     nullptr, TAG_HCAT, 256, C3, N, HD, HD,
                                     b_sage_l, TAG_H, 256, C3);

    // 8-9) batchnorm statistics -> per-channel scale/shift
    bn_zero<<<1, 384>>>();
    dim3 bs(32, 8), bg(C3 / 32, 128);
    bn_stats<<<bg, bs>>>(N);
    bn_scale<<<1, 384>>>(gamma, beta, N);

    // 10-12) MLP (BN affine + relu fused into W1 A-load; relu fused into later loads)
    gemm_tc<2><<<dim3(gm, 4), 256>>>(nullptr, TAG_HCAT, 0, C3, OFF4_W1,
                                     nullptr, TAG_H1, 0, H1D, N, H1D, C3,
                                     b1, TAG_NONE, 0, 0);
    gemm_tc<1><<<dim3(gm, 2), 256>>>(nullptr, TAG_H1, 0, H1D, OFF4_W2,
                                     nullptr, TAG_H2, 0, HD, N, HD, H1D,
                                     b2, TAG_NONE, 0, 0);
    gemm_tc<1><<<dim3(gm, 1), 256>>>(nullptr, TAG_H2, 0, HD, OFF4_W3,
                                     out, TAG_NONE, 0, OUTD, N, OUTD, HD,
                                     b3, TAG_NONE, 0, 0);
}

// round 16
// speedup vs baseline: 1.0988x; 1.0988x over previous
#include <cuda_runtime.h>

#define FIN 128
#define HD  128
#define C3  384
#define H1D 256
#define OUTD 40
#define NMAX 50000
#define EMAX 800000

// fragment-interleaved weight pool offsets (in float4 units)
// per matrix: nbp * (K/8) * 32 float4s, nbp = padded Nc/8
#define OFF4_WCAT 0                        // K=128, Nc=384, nbp=48 -> 24576
#define OFF4_WSL  24576                    // K=128, Nc=128, nbp=16 ->  8192
#define OFF4_W1   32768                    // K=384, Nc=256, nbp=32 -> 49152
#define OFF4_W2   81920                    // K=256, Nc=128, nbp=16 -> 16384
#define OFF4_W3   98304                    // K=128, Nc=40->64, nbp=8 -> 4096
#define BTOT4     102400

// ---------------- scratch (static device globals; no allocation allowed) ----
__device__ __align__(16) float g_H[(size_t)NMAX * C3];     // [x@Wgat | x@Wgcn | x@Wsage_r]
__device__ __align__(16) float g_hcat[(size_t)NMAX * C3];  // [gat_out | gcn_out | sage_out]
__device__ __align__(16) float g_sage[(size_t)NMAX * HD];  // mean of x over in-neighbors
__device__ __align__(16) float g_h1[(size_t)NMAX * H1D];
__device__ __align__(16) float g_h2[(size_t)NMAX * HD];
__device__ __align__(16) float4 g_Bfrag[BTOT4];            // mma-fragment-ordered weights
__device__ __align__(16) float4 g_csr[EMAX];               // {src, wg, wc, -}
__device__ float g_as[NMAX], g_ad[NMAX], g_dinv[NMAX], g_es[NMAX];
__device__ int   g_deg[NMAX];
__device__ int   g_off[NMAX + 1], g_cur[NMAX];
__device__ float g_sums[C3], g_sumsq[C3], g_scale[C3], g_shift[C3];
__device__ int   g_is64;   // 1 if edge_index buffer is int64, 0 if int32

// device-side scratch-buffer resolver (host never needs the addresses)
#define TAG_NONE  (-1)
#define TAG_H     0
#define TAG_HCAT  1
#define TAG_SAGE  2
#define TAG_H1    3
#define TAG_H2    4
__device__ __forceinline__ float* buf(int tag) {
    switch (tag) {
        case TAG_H:    return g_H;
        case TAG_HCAT: return g_hcat;
        case TAG_SAGE: return g_sage;
        case TAG_H1:   return g_h1;
        case TAG_H2:   return g_h2;
    }
    return nullptr;
}

__device__ __forceinline__ float leaky(float x) { return x > 0.f ? x : 0.2f * x; }

// edge-index accessor robust to int32-vs-int64 storage
__device__ __forceinline__ int ld_idx(const void* ei, size_t i) {
    if (g_is64) return (int)((const long long*)ei)[i];
    return ((const int*)ei)[i];
}

// ---------------- tf32 / mma / cp.async helpers -----------------------------
__device__ __forceinline__ unsigned f32_tf32(float f) {
    unsigned r; asm("cvt.rna.tf32.f32 %0, %1;" : "=r"(r) : "f"(f)); return r;
}
// precise split (pre-pack only)
__device__ __forceinline__ void split_tf32(float v, unsigned& hi, unsigned& lo) {
    hi = f32_tf32(v);
    lo = f32_tf32(v - __uint_as_float(hi));
}
// fast split: truncate to tf32 bits (LOP3) + exact remainder (FADD).
__device__ __forceinline__ void split_fast(float v, unsigned& hi, unsigned& lo) {
    hi = __float_as_uint(v) & 0xffffe000u;
    lo = __float_as_uint(v - __uint_as_float(hi));
}
__device__ __forceinline__ void mma8(float* c, const unsigned* a, const unsigned* b) {
    asm volatile(
        "mma.sync.aligned.m16n8k8.row.col.f32.tf32.tf32.f32 "
        "{%0,%1,%2,%3}, {%4,%5,%6,%7}, {%8,%9}, {%0,%1,%2,%3};"
        : "+f"(c[0]), "+f"(c[1]), "+f"(c[2]), "+f"(c[3])
        : "r"(a[0]), "r"(a[1]), "r"(a[2]), "r"(a[3]), "r"(b[0]), "r"(b[1]));
}
__device__ __forceinline__ void cp16(unsigned dst, const void* src, int bytes) {
    asm volatile("cp.async.cg.shared.global [%0], [%1], 16, %2;"
                 :: "r"(dst), "l"(src), "r"(bytes));
}
__device__ __forceinline__ void cp_commit() { asm volatile("cp.async.commit_group;"); }
__device__ __forceinline__ void cp_wait0()  { asm volatile("cp.async.wait_group 0;" ::: "memory"); }

// ---------------- dtype detect: odd 32-bit words all zero  <=>  int64 -------
__global__ void detect_idx(const void* ei, int E)
{
    const int* w = (const int*)ei;
    int n = E < 128 ? E : 128;
    int t = threadIdx.x;            // 128 threads
    int nz = 0;
    if (t < n) nz = (w[2 * t + 1] != 0) ? 1 : 0;
    #pragma unroll
    for (int o = 16; o; o >>= 1) nz += __shfl_xor_sync(0xffffffffu, nz, o);
    __shared__ int sh[4];
    if ((t & 31) == 0) sh[t >> 5] = nz;
    __syncthreads();
    if (t == 0) g_is64 = ((sh[0] + sh[1] + sh[2] + sh[3]) == 0) ? 1 : 0;
}

// ---------------- zero the fragment pool (for padded regions) ---------------
__global__ void zero_pool()
{
    int i = blockIdx.x * blockDim.x + threadIdx.x;
    if (i < BTOT4) g_Bfrag[i] = make_float4(0.f, 0.f, 0.f, 0.f);
}

// write one weight element into the fragment-interleaved pool
__device__ __forceinline__ void frag_store(int off4, int kctot, int k, int n, float v)
{
    unsigned hi, lo; split_tf32(v, hi, lo);
    int kc8 = k >> 3, r = k & 7, tig = r & 3, slot = r >> 2;
    int nb = n >> 3, gid = n & 7;
    int lane = gid * 4 + tig;
    float* p = (float*)(g_Bfrag + off4 + ((size_t)nb * kctot + kc8) * 32 + lane);
    p[slot]     = __uint_as_float(hi);
    p[2 + slot] = __uint_as_float(lo);
}

// ---------------- pack WCAT = [W_gat | W_gcn | W_sage_r] --------------------
__global__ void pack_split_w(const float* __restrict__ a, const float* __restrict__ b,
                             const float* __restrict__ c)
{
    int i = blockIdx.x * blockDim.x + threadIdx.x;
    if (i >= FIN * C3) return;
    int k = i / C3, j = i % C3;
    float v;
    if (j < 128)      v = a[k * HD + j];
    else if (j < 256) v = b[k * HD + j - 128];
    else              v = c[k * HD + j - 256];
    frag_store(OFF4_WCAT, FIN / 8, k, j, v);
}

// ---------------- split an external weight matrix [K, Nc] row-major ---------
__global__ void split_mat(const float* __restrict__ src, int off4, int K, int Nc)
{
    int i = blockIdx.x * blockDim.x + threadIdx.x;
    if (i >= K * Nc) return;
    int k = i / Nc, n = i % Nc;
    frag_store(off4, K >> 3, k, n, src[i]);
}

// ---------------- node init: a_src/a_dst dots, seeds ------------------------
__global__ void node_init(const float* __restrict__ att_s,
                          const float* __restrict__ att_d, int N)
{
    int gw   = (blockIdx.x * blockDim.x + threadIdx.x) >> 5;
    int lane = threadIdx.x & 31;
    if (gw >= N) return;
    float4 h = ((const float4*)(g_H + (size_t)gw * C3))[lane];   // first 128 = gat h
    float4 s = ((const float4*)att_s)[lane];
    float4 d = ((const float4*)att_d)[lane];
    float ps = h.x * s.x + h.y * s.y + h.z * s.z + h.w * s.w;
    float pd = h.x * d.x + h.y * d.y + h.z * d.z + h.w * d.w;
    #pragma unroll
    for (int o = 16; o; o >>= 1) {
        ps += __shfl_xor_sync(0xffffffffu, ps, o);
        pd += __shfl_xor_sync(0xffffffffu, pd, o);
    }
    if (lane == 0) {
        g_as[gw] = ps; g_ad[gw] = pd;
        g_deg[gw] = 1;                      // self loop counts for GCN degree
    }
}

// ---------------- edge pass 1: degree only ----------------------------------
// GAT softmax without max-subtraction: logits bounded (|e| << 80) so exp()
// cannot overflow; alpha = exp(e)/sum exp(e) is mathematically identical.
__global__ void edge_pass1(const void* __restrict__ ei, int E)
{
    int e = blockIdx.x * blockDim.x + threadIdx.x;
    if (e >= E) return;
    int d = ld_idx(ei, (size_t)E + e);
    atomicAdd(&g_deg[d], 1);     // in-degree+1; CSR count = deg-1
}

// ---------------- node scalars: es (self-loop weight), dinv ------------------
__global__ void node_seed(int N)
{
    int i = blockIdx.x * blockDim.x + threadIdx.x;
    if (i >= N) return;
    g_es[i]   = expf(leaky(g_as[i] + g_ad[i]));
    g_dinv[i] = rsqrtf((float)g_deg[i]);
}

// ---------------- exclusive scan of (deg-1) -> off, cur (single block) ------
__global__ void scan_cnt(int N, int E)
{
    __shared__ int part[1024];
    int t = threadIdx.x;
    int chunk = (N + 1023) / 1024;
    int lo = t * chunk;
    int hi = lo + chunk; if (hi > N) hi = N;
    int s = 0;
    for (int i = lo; i < hi; i++) s += g_deg[i] - 1;
    part[t] = s;
    __syncthreads();
    for (int o = 1; o < 1024; o <<= 1) {
        int v = (t >= o) ? part[t - o] : 0;
        __syncthreads();
        part[t] += v;
        __syncthreads();
    }
    int base = (t == 0) ? 0 : part[t - 1];
    for (int i = lo; i < hi; i++) {
        g_off[i] = base;
        g_cur[i] = base;
        base += g_deg[i] - 1;
    }
    if (t == 0) g_off[N] = E;
}

// ---------------- fill CSR: per-edge meta {src, wg, wc} ---------------------
__global__ void edge_fill(const void* __restrict__ ei, int E)
{
    int e = blockIdx.x * blockDim.x + threadIdx.x;
    if (e >= E) return;
    int s = ld_idx(ei, e);
    int d = ld_idx(ei, (size_t)E + e);
    float wg = expf(leaky(g_as[s] + g_ad[d]));
    float wc = g_dinv[s] * g_dinv[d];
    int pos = atomicAdd(&g_cur[d], 1);
    g_csr[pos] = make_float4(__int_as_float(s), wg, wc, 0.f);
}

// ---------------- gather: one warp per dst node (no float atomics) ----------
__global__ void gather(const float* __restrict__ x,
                       const float* __restrict__ bg,
                       const float* __restrict__ bc, int N)
{
    int gw   = (blockIdx.x * blockDim.x + threadIdx.x) >> 5;
    int lane = threadIdx.x & 31;
    if (gw >= N) return;

    const float4* hr = (const float4*)(g_H + (size_t)gw * C3);
    float es   = g_es[gw];
    float dinv = g_dinv[gw];
    float d2   = dinv * dinv;

    // self-loop seeds
    float4 hg = hr[lane];
    float4 hc = hr[lane + 32];
    float ag0 = es * hg.x, ag1 = es * hg.y, ag2 = es * hg.z, ag3 = es * hg.w;
    float ac0 = d2 * hc.x, ac1 = d2 * hc.y, ac2 = d2 * hc.z, ac3 = d2 * hc.w;
    float ax0 = 0.f, ax1 = 0.f, ax2 = 0.f, ax3 = 0.f;
    float denom = es;

    int lo = g_off[gw], hi = g_off[gw + 1];
    for (int j = lo; j < hi; j++) {
        float4 meta;
        if (lane == 0) meta = g_csr[j];
        int   s  = __shfl_sync(0xffffffffu, __float_as_int(meta.x), 0);
        float wg = __shfl_sync(0xffffffffu, meta.y, 0);
        float wc = __shfl_sync(0xffffffffu, meta.z, 0);
        const float4* hs = (const float4*)(g_H + (size_t)s * C3);
        float4 vg = hs[lane];
        float4 vc = hs[lane + 32];
        float4 vx = ((const float4*)(x + (size_t)s * FIN))[lane];
        ag0 = fmaf(wg, vg.x, ag0); ag1 = fmaf(wg, vg.y, ag1);
        ag2 = fmaf(wg, vg.z, ag2); ag3 = fmaf(wg, vg.w, ag3);
        ac0 = fmaf(wc, vc.x, ac0); ac1 = fmaf(wc, vc.y, ac1);
        ac2 = fmaf(wc, vc.z, ac2); ac3 = fmaf(wc, vc.w, ac3);
        ax0 += vx.x; ax1 += vx.y; ax2 += vx.z; ax3 += vx.w;
        denom += wg;
    }

    float inv = 1.f / denom;
    float ci  = 1.f / fmaxf((float)(hi - lo), 1.f);
    float4 b  = ((const float4*)bg)[lane];
    float4 b2 = ((const float4*)bc)[lane];
    float4* oc = (float4*)(g_hcat + (size_t)gw * C3);
    oc[lane]      = make_float4(ag0 * inv + b.x,  ag1 * inv + b.y,
                                ag2 * inv + b.z,  ag3 * inv + b.w);
    oc[lane + 32] = make_float4(ac0 + b2.x, ac1 + b2.y, ac2 + b2.z, ac3 + b2.w);
    ((float4*)(g_sage + (size_t)gw * HD))[lane] =
        make_float4(ax0 * ci, ax1 * ci, ax2 * ci, ax3 * ci);
}

// ---------------- BatchNorm stats ------------------------------------------
__global__ void bn_zero()
{
    int t = threadIdx.x;
    if (t < C3) { g_sums[t] = 0.f; g_sumsq[t] = 0.f; }
}

__global__ void bn_stats(int N)
{
    int c = blockIdx.x * 32 + threadIdx.x;
    float s = 0.f, q = 0.f;
    for (int r = blockIdx.y * blockDim.y + threadIdx.y; r < N; r += gridDim.y * blockDim.y) {
        float v = g_hcat[(size_t)r * C3 + c];
        s += v; q += v * v;
    }
    __shared__ float sh[8][33], shq[8][33];
    sh[threadIdx.y][threadIdx.x] = s;
    shq[threadIdx.y][threadIdx.x] = q;
    __syncthreads();
    if (threadIdx.y == 0) {
        #pragma unroll
        for (int j = 1; j < 8; j++) { s += sh[j][threadIdx.x]; q += shq[j][threadIdx.x]; }
        atomicAdd(&g_sums[c], s);
        atomicAdd(&g_sumsq[c], q);
    }
}

__global__ void bn_scale(const float* __restrict__ gamma,
                         const float* __restrict__ beta, int N)
{
    int c = threadIdx.x;
    if (c >= C3) return;
    float invN = 1.f / (float)N;
    float mu  = g_sums[c] * invN;
    float var = g_sumsq[c] * invN - mu * mu;
    float sc  = gamma[c] * rsqrtf(var + 1e-5f);
    g_scale[c] = sc;
    g_shift[c] = beta[c] - mu * sc;
}

// ---------------- 3xTF32 tensor-core GEMM (fragment pool staged via smem) ---
// C[M,Nc] = act(A[M,K]) @ B[K,Nc] (+bias) (+Dadd)
// B lives in g_Bfrag (mma-fragment-interleaved hi/lo); each 16-K chunk's
// 64-col slice (8 KB) is cp.async-staged into smem double buffer; inner loop
// does ONE LDS.128 per (kk,nt) — conflict-free, fully prefetched.
// 128x64 block tile, 8 warps (4x2), warp tile 32x32 via m16n8k8 tf32 mma.
// MODE 0: identity ; MODE 1: relu(A) ; MODE 2: relu(A*g_scale[k]+g_shift[k])
// Requires K % 16 == 0.
#define ASTR 20   // A smem row stride (floats): conflict-free, 16B-aligned
template<int MODE>
__global__ void __launch_bounds__(256) gemm_tc(
    const float* __restrict__ Aext, int Atag, int Aoff, int lda,
    int Boff4,
    float* __restrict__ Cext, int Ctag, int Coff, int ldc,
    int M, int Nc, int K,
    const float* __restrict__ bias,
    int Dtag, int Doff, int ldd)
{
    const float* A  = Aext ? Aext : (const float*)(buf(Atag) + Aoff);
    float*       C  = Cext ? Cext : (buf(Ctag) + Coff);
    const float* Dadd = (Dtag >= 0) ? (const float*)(buf(Dtag) + Doff) : nullptr;

    __shared__ float  As[2][128 * ASTR];
    __shared__ float4 Bs4[2][512];    // 8 nb-groups x 2 kc8 x 32 lanes

    const int t    = threadIdx.x;
    const int lane = t & 31, w = t >> 5;
    const int wm = w >> 1, wn = w & 1;          // 4x2 warp grid
    const int gid = lane >> 2, tig = lane & 3;  // fragment coords
    const int rowBase = blockIdx.x * 128;
    const int colBase = blockIdx.y * 64;
    const int kctot = K >> 3;
    const int nbBase = colBase >> 3;

    float acc[2][4][4];
    #pragma unroll
    for (int i = 0; i < 2; i++)
        #pragma unroll
        for (int j = 0; j < 4; j++)
            #pragma unroll
            for (int q = 0; q < 4; q++) acc[i][j][q] = 0.f;

    // cp.async coordinates for A (fixed per thread)
    const int ar0 = t >> 2;                 // A rows 0..63
    const int ar1 = (t + 256) >> 2;         // A rows 64..127
    const int akc = (t & 3) << 2;           // A k offset {0,4,8,12}
    const int gAr0 = rowBase + ar0, gAr1 = rowBase + ar1;
    const int szA0 = (gAr0 < M) ? 16 : 0;
    const int szA1 = (gAr1 < M) ? 16 : 0;
    const unsigned dA0 = (unsigned)__cvta_generic_to_shared(&As[0][ar0 * ASTR + akc]);
    const unsigned dA1 = (unsigned)__cvta_generic_to_shared(&As[0][ar1 * ASTR + akc]);
    const unsigned stA = (unsigned)(128 * ASTR * 4);   // stage byte stride

    // cp.async coordinates for B fragments: 512 float4/chunk, 2 per thread
    const int nbkc0 = t >> 5, nbkc1 = nbkc0 + 8;       // 0..15 slots
    const int lane4 = t & 31;
    const float4* __restrict__ Bpool = g_Bfrag + Boff4;
    const float4* srcB0 = Bpool + ((size_t)(nbBase + (nbkc0 >> 1)) * kctot + (nbkc0 & 1)) * 32 + lane4;
    const float4* srcB1 = Bpool + ((size_t)(nbBase + (nbkc1 >> 1)) * kctot + (nbkc1 & 1)) * 32 + lane4;
    const unsigned dB0 = (unsigned)__cvta_generic_to_shared(&Bs4[0][t]);
    const unsigned dB1 = (unsigned)__cvta_generic_to_shared(&Bs4[0][t + 256]);
    const unsigned stB = (unsigned)(512 * 16);

    const int nch = K >> 4;

    // prefetch chunk 0 into stage 0
    cp16(dA0, A + (size_t)gAr0 * lda + akc, szA0);
    cp16(dA1, A + (size_t)gAr1 * lda + akc, szA1);
    cp16(dB0, srcB0, 16);
    cp16(dB1, srcB1, 16);
    cp_commit();
    cp_wait0();
    __syncthreads();

    int st = 0;
    for (int c = 0; c < nch; c++) {
        int kb = c << 4;
        if (c + 1 < nch) {
            int kn = kb + 16;
            int kc8n = kn >> 3;
            unsigned soA = (st ^ 1) ? stA : 0u;
            unsigned soB = (st ^ 1) ? stB : 0u;
            cp16(dA0 + soA, A + (size_t)gAr0 * lda + kn + akc, szA0);
            cp16(dA1 + soA, A + (size_t)gAr1 * lda + kn + akc, szA1);
            cp16(dB0 + soB, srcB0 + (size_t)kc8n * 32, 16);
            cp16(dB1 + soB, srcB1 + (size_t)kc8n * 32, 16);
            cp_commit();
        }
        const float*  Ab = As[st];
        const float4* Bb = Bs4[st];
        #pragma unroll
        for (int kk = 0; kk < 16; kk += 8) {
            const int kcl = kk >> 3;
            // B fragments: one LDS.128 per nt
            unsigned bh[4][2], bl[4][2];
            #pragma unroll
            for (int nt = 0; nt < 4; nt++) {
                float4 q = Bb[(((wn * 4 + nt) * 2 + kcl) << 5) + lane];
                bh[nt][0] = __float_as_uint(q.x);
                bh[nt][1] = __float_as_uint(q.y);
                bl[nt][0] = __float_as_uint(q.z);
                bl[nt][1] = __float_as_uint(q.w);
            }
            unsigned ah[2][4], al[2][4];
            #pragma unroll
            for (int mt = 0; mt < 2; mt++) {
                const float* p = Ab + (wm * 32 + mt * 16 + gid) * ASTR + kk + tig;
                float v0 = p[0], v1 = p[8 * ASTR], v2 = p[4], v3 = p[8 * ASTR + 4];
                if (MODE == 1) {
                    v0 = fmaxf(v0, 0.f); v1 = fmaxf(v1, 0.f);
                    v2 = fmaxf(v2, 0.f); v3 = fmaxf(v3, 0.f);
                }
                if (MODE == 2) {
                    int k0g = kb + kk + tig, k1g = k0g + 4;
                    float s0 = g_scale[k0g], h0 = g_shift[k0g];
                    float s1 = g_scale[k1g], h1 = g_shift[k1g];
                    v0 = fmaxf(fmaf(v0, s0, h0), 0.f);
                    v1 = fmaxf(fmaf(v1, s0, h0), 0.f);
                    v2 = fmaxf(fmaf(v2, s1, h1), 0.f);
                    v3 = fmaxf(fmaf(v3, s1, h1), 0.f);
                }
                split_fast(v0, ah[mt][0], al[mt][0]);
                split_fast(v1, ah[mt][1], al[mt][1]);
                split_fast(v2, ah[mt][2], al[mt][2]);
                split_fast(v3, ah[mt][3], al[mt][3]);
            }
            #pragma unroll
            for (int mt = 0; mt < 2; mt++)
                #pragma unroll
                for (int nt = 0; nt < 4; nt++) {
                    mma8(acc[mt][nt], ah[mt], bh[nt]);
                    mma8(acc[mt][nt], ah[mt], bl[nt]);
                    mma8(acc[mt][nt], al[mt], bh[nt]);
                }
        }
        if (c + 1 < nch) {
            cp_wait0();
            __syncthreads();
            st ^= 1;
        }
    }

    // epilogue
    #pragma unroll
    for (int mt = 0; mt < 2; mt++) {
        int r0 = rowBase + wm * 32 + mt * 16 + gid;
        int r1 = r0 + 8;
        #pragma unroll
        for (int nt = 0; nt < 4; nt++) {
            int c0 = colBase + wn * 32 + nt * 8 + 2 * tig;
            if (c0 >= Nc) continue;
            float b0v = bias ? bias[c0] : 0.f;
            float b1v = bias ? bias[c0 + 1] : 0.f;
            if (r0 < M) {
                float v0 = acc[mt][nt][0] + b0v;
                float v1 = acc[mt][nt][1] + b1v;
                if (Dadd) {
                    v0 += Dadd[(size_t)r0 * ldd + c0];
                    v1 += Dadd[(size_t)r0 * ldd + c0 + 1];
                }
                C[(size_t)r0 * ldc + c0]     = v0;
                C[(size_t)r0 * ldc + c0 + 1] = v1;
            }
            if (r1 < M) {
                float v2 = acc[mt][nt][2] + b0v;
                float v3 = acc[mt][nt][3] + b1v;
                if (Dadd) {
                    v2 += Dadd[(size_t)r1 * ldd + c0];
                    v3 += Dadd[(size_t)r1 * ldd + c0 + 1];
                }
                C[(size_t)r1 * ldc + c0]     = v2;
                C[(size_t)r1 * ldc + c0 + 1] = v3;
            }
        }
    }
}

// ---------------- launch ----------------------------------------------------
extern "C" void kernel_launch(void* const* d_in, const int* in_sizes, int n_in,
                              void* d_out, int out_size)
{
    const float* x        = (const float*)d_in[0];
    const void*  ei       = d_in[1];
    const float* W_gat    = (const float*)d_in[2];
    const float* att_src  = (const float*)d_in[3];
    const float* att_dst  = (const float*)d_in[4];
    const float* b_gat    = (const float*)d_in[5];
    const float* W_gcn    = (const float*)d_in[6];
    const float* b_gcn    = (const float*)d_in[7];
    const float* W_sage_l = (const float*)d_in[8];
    const float* b_sage_l = (const float*)d_in[9];
    const float* W_sage_r = (const float*)d_in[10];
    const float* W1       = (const float*)d_in[11];
    const float* b1       = (const float*)d_in[12];
    const float* W2       = (const float*)d_in[13];
    const float* b2       = (const float*)d_in[14];
    const float* W3       = (const float*)d_in[15];
    const float* b3       = (const float*)d_in[16];
    const float* gamma    = (const float*)d_in[17];
    const float* beta     = (const float*)d_in[18];
    float* out = (float*)d_out;

    int N = in_sizes[0] / FIN;
    int E = in_sizes[1] / 2;

    // 0) build fragment-interleaved weight pool (zero first for padding)
    zero_pool<<<(BTOT4 + 255) / 256, 256>>>();
    pack_split_w<<<(FIN * C3 + 255) / 256, 256>>>(W_gat, W_gcn, W_sage_r);
    split_mat<<<(HD * HD + 255) / 256, 256>>>(W_sage_l, OFF4_WSL, HD, HD);
    split_mat<<<(C3 * H1D + 255) / 256, 256>>>(W1, OFF4_W1, C3, H1D);
    split_mat<<<(H1D * HD + 255) / 256, 256>>>(W2, OFF4_W2, H1D, HD);
    split_mat<<<(HD * OUTD + 255) / 256, 256>>>(W3, OFF4_W3, HD, OUTD);

    int gm = (N + 127) / 128;

    // 1) H = x @ [W_gat | W_gcn | W_sage_r]  (one merged GEMM, Nc=384)
    gemm_tc<0><<<dim3(gm, 6), 256>>>(x, TAG_NONE, 0, FIN, OFF4_WCAT,
                                     nullptr, TAG_H, 0, C3, N, C3, FIN,
                                     nullptr, TAG_NONE, 0, 0);

    // 2-6) graph aggregation via CSR gather
    detect_idx<<<1, 128>>>(ei, E);
    node_init<<<(N + 7) / 8, 256>>>(att_src, att_dst, N);
    edge_pass1<<<(E + 255) / 256, 256>>>(ei, E);
    node_seed<<<(N + 255) / 256, 256>>>(N);
    scan_cnt<<<1, 1024>>>(N, E);
    edge_fill<<<(E + 255) / 256, 256>>>(ei, E);
    gather<<<(N + 7) / 8, 256>>>(x, b_gat, b_gcn, N);

    // 7) sage: hcat[:,256:384] = mean @ W_sage_l + b_sage_l + (x@W_sage_r)
    gemm_tc<0><<<dim3(gm, 2), 256>>>(nullptr, TAG_SAGE, 0, HD, OFF4_WSL,
                                     nullptr, TAG_HCAT, 256, C3, N, HD, HD,
                                     b_sage_l, TAG_H, 256, C3);

    // 8-9) batchnorm statistics -> per-channel scale/shift
    bn_zero<<<1, 384>>>();
    dim3 bs(32, 8), bg(C3 / 32, 128);
    bn_stats<<<bg, bs>>>(N);
    bn_scale<<<1, 384>>>(gamma, beta, N);

    // 10-12) MLP (BN affine + relu fused into W1 A-load; relu fused into later loads)
    gemm_tc<2><<<dim3(gm, 4), 256>>>(nullptr, TAG_HCAT, 0, C3, OFF4_W1,
                                     nullptr, TAG_H1, 0, H1D, N, H1D, C3,
                                     b1, TAG_NONE, 0, 0);
    gemm_tc<1><<<dim3(gm, 2), 256>>>(nullptr, TAG_H1, 0, H1D, OFF4_W2,
                                     nullptr, TAG_H2, 0, HD, N, HD, H1D,
                                     b2, TAG_NONE, 0, 0);
    gemm_tc<1><<<dim3(gm, 1), 256>>>(nullptr, TAG_H2, 0, HD, OFF4_W3,
                                     out, TAG_NONE, 0, OUTD, N, OUTD, HD,
                                     b3, TAG_NONE, 0, 0);
}

// round 17
// speedup vs baseline: 1.1264x; 1.0251x over previous
#include <cuda_runtime.h>

#define FIN 128
#define HD  128
#define C3  384
#define H1D 256
#define OUTD 40
#define NMAX 50000
#define EMAX 800000

// fragment-interleaved weight pool offsets (in float4 units)
// per matrix: nbp * (K/8) * 32 float4s, nbp = padded Nc/8
#define OFF4_WGAT 0                        // K=128, Nc=128 ->  8192
#define OFF4_WGCN 8192                     // K=128, Nc=128 ->  8192
#define OFF4_WSL  16384                    // K=128, Nc=128 ->  8192
#define OFF4_WSR  24576                    // K=128, Nc=128 ->  8192
#define OFF4_W1   32768                    // K=384, Nc=256 -> 49152
#define OFF4_W2   81920                    // K=256, Nc=128 -> 16384
#define OFF4_W3   98304                    // K=128, Nc=40->64 -> 4096
#define BTOT4     102400

// ---------------- scratch (static device globals; no allocation allowed) ----
__device__ __align__(16) float g_pre[(size_t)NMAX * C3];   // [gat_pre | gcn_pre | sage_mean]
__device__ __align__(16) float g_hcat[(size_t)NMAX * C3];  // [gat_out | gcn_out | sage_out]
__device__ __align__(16) float g_h1[(size_t)NMAX * H1D];
__device__ __align__(16) float g_h2[(size_t)NMAX * HD];    // also x@W_sage_r scratch
__device__ __align__(16) float4 g_Bfrag[BTOT4];            // mma-fragment-ordered weights
__device__ __align__(16) float4 g_csr[EMAX];               // {src, wg, wc, -}
__device__ float g_as[NMAX], g_ad[NMAX], g_dinv[NMAX], g_es[NMAX];
__device__ float g_ws[FIN], g_wd[FIN];                     // W_gat @ att_src / att_dst
__device__ int   g_deg[NMAX];
__device__ int   g_off[NMAX + 1], g_cur[NMAX];
__device__ float g_sums[C3], g_sumsq[C3], g_scale[C3], g_shift[C3];
__device__ int   g_is64;   // 1 if edge_index buffer is int64, 0 if int32

// device-side scratch-buffer resolver (host never needs the addresses)
#define TAG_NONE  (-1)
#define TAG_PRE   0
#define TAG_HCAT  1
#define TAG_H1    3
#define TAG_H2    4
__device__ __forceinline__ float* buf(int tag) {
    switch (tag) {
        case TAG_PRE:  return g_pre;
        case TAG_HCAT: return g_hcat;
        case TAG_H1:   return g_h1;
        case TAG_H2:   return g_h2;
    }
    return nullptr;
}

__device__ __forceinline__ float leaky(float x) { return x > 0.f ? x : 0.2f * x; }

// edge-index accessor robust to int32-vs-int64 storage
__device__ __forceinline__ int ld_idx(const void* ei, size_t i) {
    if (g_is64) return (int)((const long long*)ei)[i];
    return ((const int*)ei)[i];
}

// ---------------- tf32 / mma / cp.async helpers -----------------------------
__device__ __forceinline__ unsigned f32_tf32(float f) {
    unsigned r; asm("cvt.rna.tf32.f32 %0, %1;" : "=r"(r) : "f"(f)); return r;
}
// precise split (pre-pack only)
__device__ __forceinline__ void split_tf32(float v, unsigned& hi, unsigned& lo) {
    hi = f32_tf32(v);
    lo = f32_tf32(v - __uint_as_float(hi));
}
// fast split: truncate to tf32 bits (LOP3) + exact remainder (FADD).
__device__ __forceinline__ void split_fast(float v, unsigned& hi, unsigned& lo) {
    hi = __float_as_uint(v) & 0xffffe000u;
    lo = __float_as_uint(v - __uint_as_float(hi));
}
__device__ __forceinline__ void mma8(float* c, const unsigned* a, const unsigned* b) {
    asm volatile(
        "mma.sync.aligned.m16n8k8.row.col.f32.tf32.tf32.f32 "
        "{%0,%1,%2,%3}, {%4,%5,%6,%7}, {%8,%9}, {%0,%1,%2,%3};"
        : "+f"(c[0]), "+f"(c[1]), "+f"(c[2]), "+f"(c[3])
        : "r"(a[0]), "r"(a[1]), "r"(a[2]), "r"(a[3]), "r"(b[0]), "r"(b[1]));
}
__device__ __forceinline__ void cp16(unsigned dst, const void* src, int bytes) {
    asm volatile("cp.async.cg.shared.global [%0], [%1], 16, %2;"
                 :: "r"(dst), "l"(src), "r"(bytes));
}
__device__ __forceinline__ void cp_commit() { asm volatile("cp.async.commit_group;"); }
__device__ __forceinline__ void cp_wait0()  { asm volatile("cp.async.wait_group 0;" ::: "memory"); }

// ---------------- dtype detect: odd 32-bit words all zero  <=>  int64 -------
__global__ void detect_idx(const void* ei, int E)
{
    const int* w = (const int*)ei;
    int n = E < 128 ? E : 128;
    int t = threadIdx.x;            // 128 threads
    int nz = 0;
    if (t < n) nz = (w[2 * t + 1] != 0) ? 1 : 0;
    #pragma unroll
    for (int o = 16; o; o >>= 1) nz += __shfl_xor_sync(0xffffffffu, nz, o);
    __shared__ int sh[4];
    if ((t & 31) == 0) sh[t >> 5] = nz;
    __syncthreads();
    if (t == 0) g_is64 = ((sh[0] + sh[1] + sh[2] + sh[3]) == 0) ? 1 : 0;
}

// ---------------- zero the fragment pool (for padded regions) ---------------
__global__ void zero_pool()
{
    int i = blockIdx.x * blockDim.x + threadIdx.x;
    if (i < BTOT4) g_Bfrag[i] = make_float4(0.f, 0.f, 0.f, 0.f);
}

// write one weight element into the fragment-interleaved pool
__device__ __forceinline__ void frag_store(int off4, int kctot, int k, int n, float v)
{
    unsigned hi, lo; split_tf32(v, hi, lo);
    int kc8 = k >> 3, r = k & 7, tig = r & 3, slot = r >> 2;
    int nb = n >> 3, gid = n & 7;
    int lane = gid * 4 + tig;
    float* p = (float*)(g_Bfrag + off4 + ((size_t)nb * kctot + kc8) * 32 + lane);
    p[slot]     = __uint_as_float(hi);
    p[2 + slot] = __uint_as_float(lo);
}

// ---------------- split an external weight matrix [K, Nc] row-major ---------
__global__ void split_mat(const float* __restrict__ src, int off4, int K, int Nc)
{
    int i = blockIdx.x * blockDim.x + threadIdx.x;
    if (i >= K * Nc) return;
    int k = i / Nc, n = i % Nc;
    frag_store(off4, K >> 3, k, n, src[i]);
}

// ---------------- ws = W_gat @ att_src, wd = W_gat @ att_dst ----------------
__global__ void wvec(const float* __restrict__ Wg,
                     const float* __restrict__ as_,
                     const float* __restrict__ ad_)
{
    int k = threadIdx.x;           // 128 threads
    if (k >= FIN) return;
    float s = 0.f, d = 0.f;
    const float* row = Wg + k * HD;
    #pragma unroll 8
    for (int j = 0; j < HD; j++) {
        float w = row[j];
        s = fmaf(w, as_[j], s);
        d = fmaf(w, ad_[j], d);
    }
    g_ws[k] = s;
    g_wd[k] = d;
}

// ---------------- node init: a_s/a_d dots of x with ws/wd, seeds ------------
__global__ void node_init(const float* __restrict__ x, int N)
{
    int gw   = (blockIdx.x * blockDim.x + threadIdx.x) >> 5;
    int lane = threadIdx.x & 31;
    if (gw >= N) return;
    float4 h = ((const float4*)(x + (size_t)gw * FIN))[lane];
    float4 s = ((const float4*)g_ws)[lane];
    float4 d = ((const float4*)g_wd)[lane];
    float ps = h.x * s.x + h.y * s.y + h.z * s.z + h.w * s.w;
    float pd = h.x * d.x + h.y * d.y + h.z * d.z + h.w * d.w;
    #pragma unroll
    for (int o = 16; o; o >>= 1) {
        ps += __shfl_xor_sync(0xffffffffu, ps, o);
        pd += __shfl_xor_sync(0xffffffffu, pd, o);
    }
    if (lane == 0) {
        g_as[gw] = ps; g_ad[gw] = pd;
        g_deg[gw] = 1;                      // self loop counts for GCN degree
    }
}

// ---------------- edge pass 1: degree only ----------------------------------
// GAT softmax without max-subtraction: logits bounded (|e| << 80) so exp()
// cannot overflow; alpha = exp(e)/sum exp(e) is mathematically identical.
__global__ void edge_pass1(const void* __restrict__ ei, int E)
{
    int e = blockIdx.x * blockDim.x + threadIdx.x;
    if (e >= E) return;
    int d = ld_idx(ei, (size_t)E + e);
    atomicAdd(&g_deg[d], 1);     // in-degree+1; CSR count = deg-1
}

// ---------------- node scalars: es (self-loop weight), dinv ------------------
__global__ void node_seed(int N)
{
    int i = blockIdx.x * blockDim.x + threadIdx.x;
    if (i >= N) return;
    g_es[i]   = expf(leaky(g_as[i] + g_ad[i]));
    g_dinv[i] = rsqrtf((float)g_deg[i]);
}

// ---------------- exclusive scan of (deg-1) -> off, cur (single block) ------
__global__ void scan_cnt(int N, int E)
{
    __shared__ int part[1024];
    int t = threadIdx.x;
    int chunk = (N + 1023) / 1024;
    int lo = t * chunk;
    int hi = lo + chunk; if (hi > N) hi = N;
    int s = 0;
    for (int i = lo; i < hi; i++) s += g_deg[i] - 1;
    part[t] = s;
    __syncthreads();
    for (int o = 1; o < 1024; o <<= 1) {
        int v = (t >= o) ? part[t - o] : 0;
        __syncthreads();
        part[t] += v;
        __syncthreads();
    }
    int base = (t == 0) ? 0 : part[t - 1];
    for (int i = lo; i < hi; i++) {
        g_off[i] = base;
        g_cur[i] = base;
        base += g_deg[i] - 1;
    }
    if (t == 0) g_off[N] = E;
}

// ---------------- fill CSR: per-edge meta {src, wg, wc} ---------------------
__global__ void edge_fill(const void* __restrict__ ei, int E)
{
    int e = blockIdx.x * blockDim.x + threadIdx.x;
    if (e >= E) return;
    int s = ld_idx(ei, e);
    int d = ld_idx(ei, (size_t)E + e);
    float wg = expf(leaky(g_as[s] + g_ad[d]));
    float wc = g_dinv[s] * g_dinv[d];
    int pos = atomicAdd(&g_cur[d], 1);
    g_csr[pos] = make_float4(__int_as_float(s), wg, wc, 0.f);
}

// ---------------- gather in x-space: ONE x-row read per edge ----------------
// pre_gat = (es*x_i + sum wg*x_s)/denom ; pre_gcn = d2*x_i + sum wc*x_s ;
// sage_mean = (sum x_s)/cnt.  All three share the same 512B x[s] read.
__global__ void gather(const float* __restrict__ x, int N)
{
    int gw   = (blockIdx.x * blockDim.x + threadIdx.x) >> 5;
    int lane = threadIdx.x & 31;
    if (gw >= N) return;

    float es   = g_es[gw];
    float dinv = g_dinv[gw];
    float d2   = dinv * dinv;

    float4 xi = ((const float4*)(x + (size_t)gw * FIN))[lane];
    float ag0 = es * xi.x, ag1 = es * xi.y, ag2 = es * xi.z, ag3 = es * xi.w;
    float ac0 = d2 * xi.x, ac1 = d2 * xi.y, ac2 = d2 * xi.z, ac3 = d2 * xi.w;
    float ax0 = 0.f, ax1 = 0.f, ax2 = 0.f, ax3 = 0.f;
    float denom = es;

    int lo = g_off[gw], hi = g_off[gw + 1];
    for (int j = lo; j < hi; j++) {
        float4 meta;
        if (lane == 0) meta = g_csr[j];
        int   s  = __shfl_sync(0xffffffffu, __float_as_int(meta.x), 0);
        float wg = __shfl_sync(0xffffffffu, meta.y, 0);
        float wc = __shfl_sync(0xffffffffu, meta.z, 0);
        float4 vx = ((const float4*)(x + (size_t)s * FIN))[lane];
        ag0 = fmaf(wg, vx.x, ag0); ag1 = fmaf(wg, vx.y, ag1);
        ag2 = fmaf(wg, vx.z, ag2); ag3 = fmaf(wg, vx.w, ag3);
        ac0 = fmaf(wc, vx.x, ac0); ac1 = fmaf(wc, vx.y, ac1);
        ac2 = fmaf(wc, vx.z, ac2); ac3 = fmaf(wc, vx.w, ac3);
        ax0 += vx.x; ax1 += vx.y; ax2 += vx.z; ax3 += vx.w;
        denom += wg;
    }

    float inv = 1.f / denom;
    float ci  = 1.f / fmaxf((float)(hi - lo), 1.f);
    float4* pr = (float4*)(g_pre + (size_t)gw * C3);
    pr[lane]      = make_float4(ag0 * inv, ag1 * inv, ag2 * inv, ag3 * inv);
    pr[lane + 32] = make_float4(ac0, ac1, ac2, ac3);
    pr[lane + 64] = make_float4(ax0 * ci, ax1 * ci, ax2 * ci, ax3 * ci);
}

// ---------------- BatchNorm stats ------------------------------------------
__global__ void bn_zero()
{
    int t = threadIdx.x;
    if (t < C3) { g_sums[t] = 0.f; g_sumsq[t] = 0.f; }
}

__global__ void bn_stats(int N)
{
    int c = blockIdx.x * 32 + threadIdx.x;
    float s = 0.f, q = 0.f;
    for (int r = blockIdx.y * blockDim.y + threadIdx.y; r < N; r += gridDim.y * blockDim.y) {
        float v = g_hcat[(size_t)r * C3 + c];
        s += v; q += v * v;
    }
    __shared__ float sh[8][33], shq[8][33];
    sh[threadIdx.y][threadIdx.x] = s;
    shq[threadIdx.y][threadIdx.x] = q;
    __syncthreads();
    if (threadIdx.y == 0) {
        #pragma unroll
        for (int j = 1; j < 8; j++) { s += sh[j][threadIdx.x]; q += shq[j][threadIdx.x]; }
        atomicAdd(&g_sums[c], s);
        atomicAdd(&g_sumsq[c], q);
    }
}

__global__ void bn_scale(const float* __restrict__ gamma,
                         const float* __restrict__ beta, int N)
{
    int c = threadIdx.x;
    if (c >= C3) return;
    float invN = 1.f / (float)N;
    float mu  = g_sums[c] * invN;
    float var = g_sumsq[c] * invN - mu * mu;
    float sc  = gamma[c] * rsqrtf(var + 1e-5f);
    g_scale[c] = sc;
    g_shift[c] = beta[c] - mu * sc;
}

// ---------------- 3xTF32 tensor-core GEMM (fragment pool staged via smem) ---
// C[M,Nc] = act(A[M,K]) @ B[K,Nc] (+bias) (+Dadd)
// B lives in g_Bfrag (mma-fragment-interleaved hi/lo); each 16-K chunk's
// 64-col slice (8 KB) is cp.async-staged into smem double buffer; inner loop
// does ONE LDS.128 per (kk,nt) — conflict-free, fully prefetched.
// 128x64 block tile, 8 warps (4x2), warp tile 32x32 via m16n8k8 tf32 mma.
// MODE 0: identity ; MODE 1: relu(A) ; MODE 2: relu(A*g_scale[k]+g_shift[k])
// Requires K % 16 == 0.
#define ASTR 20   // A smem row stride (floats): conflict-free, 16B-aligned
template<int MODE>
__global__ void __launch_bounds__(256) gemm_tc(
    const float* __restrict__ Aext, int Atag, int Aoff, int lda,
    int Boff4,
    float* __restrict__ Cext, int Ctag, int Coff, int ldc,
    int M, int Nc, int K,
    const float* __restrict__ bias,
    int Dtag, int Doff, int ldd)
{
    const float* A  = Aext ? Aext : (const float*)(buf(Atag) + Aoff);
    float*       C  = Cext ? Cext : (buf(Ctag) + Coff);
    const float* Dadd = (Dtag >= 0) ? (const float*)(buf(Dtag) + Doff) : nullptr;

    __shared__ float  As[2][128 * ASTR];
    __shared__ float4 Bs4[2][512];    // 8 nb-groups x 2 kc8 x 32 lanes

    const int t    = threadIdx.x;
    const int lane = t & 31, w = t >> 5;
    const int wm = w >> 1, wn = w & 1;          // 4x2 warp grid
    const int gid = lane >> 2, tig = lane & 3;  // fragment coords
    const int rowBase = blockIdx.x * 128;
    const int colBase = blockIdx.y * 64;
    const int kctot = K >> 3;
    const int nbBase = colBase >> 3;

    float acc[2][4][4];
    #pragma unroll
    for (int i = 0; i < 2; i++)
        #pragma unroll
        for (int j = 0; j < 4; j++)
            #pragma unroll
            for (int q = 0; q < 4; q++) acc[i][j][q] = 0.f;

    // cp.async coordinates for A (fixed per thread)
    const int ar0 = t >> 2;                 // A rows 0..63
    const int ar1 = (t + 256) >> 2;         // A rows 64..127
    const int akc = (t & 3) << 2;           // A k offset {0,4,8,12}
    const int gAr0 = rowBase + ar0, gAr1 = rowBase + ar1;
    const int szA0 = (gAr0 < M) ? 16 : 0;
    const int szA1 = (gAr1 < M) ? 16 : 0;
    const unsigned dA0 = (unsigned)__cvta_generic_to_shared(&As[0][ar0 * ASTR + akc]);
    const unsigned dA1 = (unsigned)__cvta_generic_to_shared(&As[0][ar1 * ASTR + akc]);
    const unsigned stA = (unsigned)(128 * ASTR * 4);   // stage byte stride

    // cp.async coordinates for B fragments: 512 float4/chunk, 2 per thread
    const int nbkc0 = t >> 5, nbkc1 = nbkc0 + 8;       // 0..15 slots
    const int lane4 = t & 31;
    const float4* __restrict__ Bpool = g_Bfrag + Boff4;
    const float4* srcB0 = Bpool + ((size_t)(nbBase + (nbkc0 >> 1)) * kctot + (nbkc0 & 1)) * 32 + lane4;
    const float4* srcB1 = Bpool + ((size_t)(nbBase + (nbkc1 >> 1)) * kctot + (nbkc1 & 1)) * 32 + lane4;
    const unsigned dB0 = (unsigned)__cvta_generic_to_shared(&Bs4[0][t]);
    const unsigned dB1 = (unsigned)__cvta_generic_to_shared(&Bs4[0][t + 256]);
    const unsigned stB = (unsigned)(512 * 16);

    const int nch = K >> 4;

    // prefetch chunk 0 into stage 0
    cp16(dA0, A + (size_t)gAr0 * lda + akc, szA0);
    cp16(dA1, A + (size_t)gAr1 * lda + akc, szA1);
    cp16(dB0, srcB0, 16);
    cp16(dB1, srcB1, 16);
    cp_commit();
    cp_wait0();
    __syncthreads();

    int st = 0;
    for (int c = 0; c < nch; c++) {
        int kb = c << 4;
        if (c + 1 < nch) {
            int kn = kb + 16;
            int kc8n = kn >> 3;
            unsigned soA = (st ^ 1) ? stA : 0u;
            unsigned soB = (st ^ 1) ? stB : 0u;
            cp16(dA0 + soA, A + (size_t)gAr0 * lda + kn + akc, szA0);
            cp16(dA1 + soA, A + (size_t)gAr1 * lda + kn + akc, szA1);
            cp16(dB0 + soB, srcB0 + (size_t)kc8n * 32, 16);
            cp16(dB1 + soB, srcB1 + (size_t)kc8n * 32, 16);
            cp_commit();
        }
        const float*  Ab = As[st];
        const float4* Bb = Bs4[st];
        #pragma unroll
        for (int kk = 0; kk < 16; kk += 8) {
            const int kcl = kk >> 3;
            // B fragments: one LDS.128 per nt
            unsigned bh[4][2], bl[4][2];
            #pragma unroll
            for (int nt = 0; nt < 4; nt++) {
                float4 q = Bb[(((wn * 4 + nt) * 2 + kcl) << 5) + lane];
                bh[nt][0] = __float_as_uint(q.x);
                bh[nt][1] = __float_as_uint(q.y);
                bl[nt][0] = __float_as_uint(q.z);
                bl[nt][1] = __float_as_uint(q.w);
            }
            unsigned ah[2][4], al[2][4];
            #pragma unroll
            for (int mt = 0; mt < 2; mt++) {
                const float* p = Ab + (wm * 32 + mt * 16 + gid) * ASTR + kk + tig;
                float v0 = p[0], v1 = p[8 * ASTR], v2 = p[4], v3 = p[8 * ASTR + 4];
                if (MODE == 1) {
                    v0 = fmaxf(v0, 0.f); v1 = fmaxf(v1, 0.f);
                    v2 = fmaxf(v2, 0.f); v3 = fmaxf(v3, 0.f);
                }
                if (MODE == 2) {
                    int k0g = kb + kk + tig, k1g = k0g + 4;
                    float s0 = g_scale[k0g], h0 = g_shift[k0g];
                    float s1 = g_scale[k1g], h1 = g_shift[k1g];
                    v0 = fmaxf(fmaf(v0, s0, h0), 0.f);
                    v1 = fmaxf(fmaf(v1, s0, h0), 0.f);
                    v2 = fmaxf(fmaf(v2, s1, h1), 0.f);
                    v3 = fmaxf(fmaf(v3, s1, h1), 0.f);
                }
                split_fast(v0, ah[mt][0], al[mt][0]);
                split_fast(v1, ah[mt][1], al[mt][1]);
                split_fast(v2, ah[mt][2], al[mt][2]);
                split_fast(v3, ah[mt][3], al[mt][3]);
            }
            #pragma unroll
            for (int mt = 0; mt < 2; mt++)
                #pragma unroll
                for (int nt = 0; nt < 4; nt++) {
                    mma8(acc[mt][nt], ah[mt], bh[nt]);
                    mma8(acc[mt][nt], ah[mt], bl[nt]);
                    mma8(acc[mt][nt], al[mt], bh[nt]);
                }
        }
        if (c + 1 < nch) {
            cp_wait0();
            __syncthreads();
            st ^= 1;
        }
    }

    // epilogue
    #pragma unroll
    for (int mt = 0; mt < 2; mt++) {
        int r0 = rowBase + wm * 32 + mt * 16 + gid;
        int r1 = r0 + 8;
        #pragma unroll
        for (int nt = 0; nt < 4; nt++) {
            int c0 = colBase + wn * 32 + nt * 8 + 2 * tig;
            if (c0 >= Nc) continue;
            float b0v = bias ? bias[c0] : 0.f;
            float b1v = bias ? bias[c0 + 1] : 0.f;
            if (r0 < M) {
                float v0 = acc[mt][nt][0] + b0v;
                float v1 = acc[mt][nt][1] + b1v;
                if (Dadd) {
                    v0 += Dadd[(size_t)r0 * ldd + c0];
                    v1 += Dadd[(size_t)r0 * ldd + c0 + 1];
                }
                C[(size_t)r0 * ldc + c0]     = v0;
                C[(size_t)r0 * ldc + c0 + 1] = v1;
            }
            if (r1 < M) {
                float v2 = acc[mt][nt][2] + b0v;
                float v3 = acc[mt][nt][3] + b1v;
                if (Dadd) {
                    v2 += Dadd[(size_t)r1 * ldd + c0];
                    v3 += Dadd[(size_t)r1 * ldd + c0 + 1];
                }
                C[(size_t)r1 * ldc + c0]     = v2;
                C[(size_t)r1 * ldc + c0 + 1] = v3;
            }
        }
    }
}

// ---------------- launch ----------------------------------------------------
extern "C" void kernel_launch(void* const* d_in, const int* in_sizes, int n_in,
                              void* d_out, int out_size)
{
    const float* x        = (const float*)d_in[0];
    const void*  ei       = d_in[1];
    const float* W_gat    = (const float*)d_in[2];
    const float* att_src  = (const float*)d_in[3];
    const float* att_dst  = (const float*)d_in[4];
    const float* b_gat    = (const float*)d_in[5];
    const float* W_gcn    = (const float*)d_in[6];
    const float* b_gcn    = (const float*)d_in[7];
    const float* W_sage_l = (const float*)d_in[8];
    const float* b_sage_l = (const float*)d_in[9];
    const float* W_sage_r = (const float*)d_in[10];
    const float* W1       = (const float*)d_in[11];
    const float* b1       = (const float*)d_in[12];
    const float* W2       = (const float*)d_in[13];
    const float* b2       = (const float*)d_in[14];
    const float* W3       = (const float*)d_in[15];
    const float* b3       = (const float*)d_in[16];
    const float* gamma    = (const float*)d_in[17];
    const float* beta     = (const float*)d_in[18];
    float* out = (float*)d_out;

    int N = in_sizes[0] / FIN;
    int E = in_sizes[1] / 2;
    int gm = (N + 127) / 128;

    // 0) build fragment-interleaved weight pool + logit vectors
    zero_pool<<<(BTOT4 + 255) / 256, 256>>>();
    split_mat<<<(FIN * HD + 255) / 256, 256>>>(W_gat, OFF4_WGAT, FIN, HD);
    split_mat<<<(FIN * HD + 255) / 256, 256>>>(W_gcn, OFF4_WGCN, FIN, HD);
    split_mat<<<(HD * HD + 255) / 256, 256>>>(W_sage_l, OFF4_WSL, HD, HD);
    split_mat<<<(FIN * HD + 255) / 256, 256>>>(W_sage_r, OFF4_WSR, FIN, HD);
    split_mat<<<(C3 * H1D + 255) / 256, 256>>>(W1, OFF4_W1, C3, H1D);
    split_mat<<<(H1D * HD + 255) / 256, 256>>>(W2, OFF4_W2, H1D, HD);
    split_mat<<<(HD * OUTD + 255) / 256, 256>>>(W3, OFF4_W3, HD, OUTD);
    wvec<<<1, 128>>>(W_gat, att_src, att_dst);
    detect_idx<<<1, 128>>>(ei, E);

    // 1) graph aggregation in x-space via CSR gather
    node_init<<<(N + 7) / 8, 256>>>(x, N);
    edge_pass1<<<(E + 255) / 256, 256>>>(ei, E);
    node_seed<<<(N + 255) / 256, 256>>>(N);
    scan_cnt<<<1, 1024>>>(N, E);
    edge_fill<<<(E + 255) / 256, 256>>>(ei, E);
    gather<<<(N + 7) / 8, 256>>>(x, N);

    // 2) x @ W_sage_r (independent of graph work) -> g_h2
    gemm_tc<0><<<dim3(gm, 2), 256>>>(x, TAG_NONE, 0, FIN, OFF4_WSR,
                                     nullptr, TAG_H2, 0, HD, N, HD, FIN,
                                     nullptr, TAG_NONE, 0, 0);

    // 3) post-aggregation GEMMs -> hcat
    gemm_tc<0><<<dim3(gm, 2), 256>>>(nullptr, TAG_PRE, 0, C3, OFF4_WGAT,
                                     nullptr, TAG_HCAT, 0, C3, N, HD, FIN,
                                     b_gat, TAG_NONE, 0, 0);
    gemm_tc<0><<<dim3(gm, 2), 256>>>(nullptr, TAG_PRE, 128, C3, OFF4_WGCN,
                                     nullptr, TAG_HCAT, 128, C3, N, HD, FIN,
                                     b_gcn, TAG_NONE, 0, 0);
    gemm_tc<0><<<dim3(gm, 2), 256>>>(nullptr, TAG_PRE, 256, C3, OFF4_WSL,
                                     nullptr, TAG_HCAT, 256, C3, N, HD, HD,
                                     b_sage_l, TAG_H2, 0, HD);

    // 4) batchnorm statistics -> per-channel scale/shift
    bn_zero<<<1, 384>>>();
    dim3 bs(32, 8), bg(C3 / 32, 128);
    bn_stats<<<bg, bs>>>(N);
    bn_scale<<<1, 384>>>(gamma, beta, N);

    // 5) MLP (BN affine + relu fused into W1 A-load; relu fused into later loads)
    gemm_tc<2><<<dim3(gm, 4), 256>>>(nullptr, TAG_HCAT, 0, C3, OFF4_W1,
                                     nullptr, TAG_H1, 0, H1D, N, H1D, C3,
                                     b1, TAG_NONE, 0, 0);
    gemm_tc<1><<<dim3(gm, 2), 256>>>(nullptr, TAG_H1, 0, H1D, OFF4_W2,
                                     nullptr, TAG_H2, 0, HD, N, HD, H1D,
                                     b2, TAG_NONE, 0, 0);
    gemm_tc<1><<<dim3(gm, 1), 256>>>(nullptr, TAG_H2, 0, HD, OFF4_W3,
                                     out, TAG_NONE, 0, OUTD, N, OUTD, HD,
                                     b3, TAG_NONE, 0, 0);
}